// round 2
// baseline (speedup 1.0000x reference)
#include <cuda_runtime.h>
#include <cuda_bf16.h>

#define NMAX 100000
#define EMAX 1600000
#define SCAN_CHUNK 1024
#define NB_MAX ((NMAX + SCAN_CHUNK - 1) / SCAN_CHUNK)

// ---------------------------------------------------------------------------
// Scratch (device globals — allocation is forbidden in kernel_launch)
// ---------------------------------------------------------------------------
__device__ int   g_deg[NMAX];
__device__ int   g_off[NMAX + 1];     // CSR row offsets (by dst)
__device__ int   g_cur[NMAX];         // fill cursors
__device__ int   g_csrc[EMAX];        // CSR column = src node per edge
__device__ int   g_bsum[NB_MAX + 1];  // block sums for scan
__device__ float g_dinv[NMAX];
__device__ float g_xs[NMAX * 4];      // x * dinv  (pre-scaled sources, layer 1)
__device__ float g_h2s[NMAX * 32];    // (relu(v@W1+b1) @ W2) * dinv  (pre-scaled, layer 2)

// ---------------------------------------------------------------------------
// K0: zero degree counters
// ---------------------------------------------------------------------------
__global__ void k_zero(int n) {
    int i = blockIdx.x * blockDim.x + threadIdx.x;
    if (i < n) g_deg[i] = 0;
}

// ---------------------------------------------------------------------------
// K1: degree over dst (self-loop handled as +1 later)
// ---------------------------------------------------------------------------
__global__ void k_deg(const int* __restrict__ dst, int E) {
    int e = blockIdx.x * blockDim.x + threadIdx.x;
    if (e < E) atomicAdd(&g_deg[dst[e]], 1);
}

// ---------------------------------------------------------------------------
// K2a: per-chunk (1024-elem) sums of deg
// ---------------------------------------------------------------------------
__global__ void k_blocksum(int n) {
    __shared__ int sh[SCAN_CHUNK];
    int t = threadIdx.x;
    int i = blockIdx.x * SCAN_CHUNK + t;
    sh[t] = (i < n) ? g_deg[i] : 0;
    __syncthreads();
    for (int o = SCAN_CHUNK / 2; o > 0; o >>= 1) {
        if (t < o) sh[t] += sh[t + o];
        __syncthreads();
    }
    if (t == 0) g_bsum[blockIdx.x] = sh[0];
}

// ---------------------------------------------------------------------------
// K2b: exclusive scan of block sums (single thread; NB <= 98) + off[n]=E
// ---------------------------------------------------------------------------
__global__ void k_scan_bsum(int nb, int n, int E) {
    if (threadIdx.x == 0 && blockIdx.x == 0) {
        int run = 0;
        for (int b = 0; b < nb; b++) {
            int v = g_bsum[b];
            g_bsum[b] = run;
            run += v;
        }
        g_off[n] = E;
    }
}

// ---------------------------------------------------------------------------
// K2c: per-chunk exclusive scan -> g_off, g_cur; also dinv and x_scaled
// ---------------------------------------------------------------------------
__global__ void k_scan(const float4* __restrict__ x4, int n) {
    __shared__ int sh[SCAN_CHUNK];
    int t = threadIdx.x;
    int i = blockIdx.x * SCAN_CHUNK + t;
    int v = (i < n) ? g_deg[i] : 0;
    sh[t] = v;
    __syncthreads();
    // Hillis-Steele inclusive scan
    for (int o = 1; o < SCAN_CHUNK; o <<= 1) {
        int y = (t >= o) ? sh[t - o] : 0;
        __syncthreads();
        sh[t] += y;
        __syncthreads();
    }
    if (i < n) {
        int exc = g_bsum[blockIdx.x] + sh[t] - v;
        g_off[i] = exc;
        g_cur[i] = exc;
        float di = rsqrtf((float)(v + 1));   // +1 self-loop
        g_dinv[i] = di;
        float4 xv = x4[i];
        xv.x *= di; xv.y *= di; xv.z *= di; xv.w *= di;
        *(float4*)&g_xs[i * 4] = xv;
    }
}

// ---------------------------------------------------------------------------
// K3: bucket-fill CSR: csrc[pos] = src[e] for each edge, grouped by dst
// ---------------------------------------------------------------------------
__global__ void k_fill(const int* __restrict__ src,
                       const int* __restrict__ dst, int E) {
    int e = blockIdx.x * blockDim.x + threadIdx.x;
    if (e >= E) return;
    int pos = atomicAdd(&g_cur[dst[e]], 1);
    g_csrc[pos] = src[e];
}

// ---------------------------------------------------------------------------
// K4: fused layer 1 (warp per node):
//     v   = dinv[d] * (sum_{s in nbr} xs[s] + xs[d])          [4]
//     h1  = relu(v @ W1 + b1)                                 [64]
//     h2s = (h1 @ W2) * dinv[d]                               [32]
// ---------------------------------------------------------------------------
__global__ void __launch_bounds__(256) k_layer1(
        const float* __restrict__ W1,   // [4,64]
        const float* __restrict__ b1,   // [64]
        const float* __restrict__ W2,   // [64,32]
        int n) {
    __shared__ float sW1[4 * 64];
    __shared__ float sb1[64];
    __shared__ float sW2[64 * 32];
    __shared__ float sh1[8][64];
    int t = threadIdx.x;
    for (int i = t; i < 256;  i += 256) sW1[i] = W1[i];
    if (t < 64) sb1[t] = b1[t];
    for (int i = t; i < 2048; i += 256) sW2[i] = W2[i];
    __syncthreads();

    int w = t >> 5, l = t & 31;
    int node = blockIdx.x * 8 + w;
    if (node >= n) return;

    int beg = g_off[node], end = g_off[node + 1];
    float a0 = 0.f, a1 = 0.f, a2 = 0.f, a3 = 0.f;
    for (int j = beg + l; j < end; j += 32) {
        int s = g_csrc[j];
        float4 xv = *(const float4*)&g_xs[s * 4];
        a0 += xv.x; a1 += xv.y; a2 += xv.z; a3 += xv.w;
    }
#pragma unroll
    for (int o = 16; o > 0; o >>= 1) {
        a0 += __shfl_xor_sync(0xffffffff, a0, o);
        a1 += __shfl_xor_sync(0xffffffff, a1, o);
        a2 += __shfl_xor_sync(0xffffffff, a2, o);
        a3 += __shfl_xor_sync(0xffffffff, a3, o);
    }
    float di = g_dinv[node];
    float4 xself = *(const float4*)&g_xs[node * 4];
    float v0 = (a0 + xself.x) * di;
    float v1 = (a1 + xself.y) * di;
    float v2 = (a2 + xself.z) * di;
    float v3 = (a3 + xself.w) * di;

    // each lane computes h1[l] and h1[l+32]
#pragma unroll
    for (int half = 0; half < 2; half++) {
        int f = l + half * 32;
        float h = fmaf(v0, sW1[f],
                  fmaf(v1, sW1[64 + f],
                  fmaf(v2, sW1[128 + f],
                  fmaf(v3, sW1[192 + f], sb1[f]))));
        sh1[w][f] = fmaxf(h, 0.0f);
    }
    __syncwarp();

    float acc = 0.0f;
#pragma unroll
    for (int f = 0; f < 64; f++)
        acc = fmaf(sh1[w][f], sW2[f * 32 + l], acc);
    g_h2s[node * 32 + l] = acc * di;
}

// ---------------------------------------------------------------------------
// K5: fused layer 2 + final linear (warp per node, lane = feature):
//     h2  = relu(dinv[d] * (sum_{s} h2s[s] + h2s[d]) + b2)    [32]
//     out = relu(h2 @ Wf + bf)                                [32]
// ---------------------------------------------------------------------------
__global__ void __launch_bounds__(256) k_final(
        const float* __restrict__ b2,   // [32]
        const float* __restrict__ Wf,   // [32,32]
        const float* __restrict__ bf,   // [32]
        float* __restrict__ out, int n) {
    __shared__ float sWf[32 * 32];
    __shared__ float sb2[32];
    __shared__ float sbf[32];
    __shared__ float sh[8][32];
    int t = threadIdx.x;
    for (int i = t; i < 1024; i += 256) sWf[i] = Wf[i];
    if (t < 32) { sb2[t] = b2[t]; sbf[t] = bf[t]; }
    __syncthreads();

    int w = t >> 5, j = t & 31;
    int node = blockIdx.x * 8 + w;
    if (node >= n) return;

    int beg = g_off[node], end = g_off[node + 1];
    float acc = 0.0f;
    int i = beg;
    // 4-edge unroll for memory-level parallelism
    for (; i + 4 <= end; i += 4) {
        int s0 = g_csrc[i];
        int s1 = g_csrc[i + 1];
        int s2 = g_csrc[i + 2];
        int s3 = g_csrc[i + 3];
        float m0 = g_h2s[s0 * 32 + j];
        float m1 = g_h2s[s1 * 32 + j];
        float m2 = g_h2s[s2 * 32 + j];
        float m3 = g_h2s[s3 * 32 + j];
        acc += (m0 + m1) + (m2 + m3);
    }
    for (; i < end; i++)
        acc += g_h2s[g_csrc[i] * 32 + j];

    float di = g_dinv[node];
    float h = fmaxf(fmaf(di, acc + g_h2s[node * 32 + j], sb2[j]), 0.0f);
    sh[w][j] = h;
    __syncwarp();

    float o = sbf[j];
#pragma unroll
    for (int k = 0; k < 32; k++)
        o = fmaf(sh[w][k], sWf[k * 32 + j], o);
    out[node * 32 + j] = fmaxf(o, 0.0f);
}

// ---------------------------------------------------------------------------
// Launch
// Inputs: x[N,4], edge_index[2,E], W1[4,64], b1[64], W2[64,32], b2[32],
//         Wf[32,32], bf[32]       Output: [N,32] float32
// ---------------------------------------------------------------------------
extern "C" void kernel_launch(void* const* d_in, const int* in_sizes, int n_in,
                              void* d_out, int out_size) {
    const float* x  = (const float*)d_in[0];
    const int*   ei = (const int*)d_in[1];
    const float* W1 = (const float*)d_in[2];
    const float* b1 = (const float*)d_in[3];
    const float* W2 = (const float*)d_in[4];
    const float* b2 = (const float*)d_in[5];
    const float* Wf = (const float*)d_in[6];
    const float* bf = (const float*)d_in[7];
    float* out = (float*)d_out;

    int n = in_sizes[0] / 4;
    int E = in_sizes[1] / 2;
    const int* src = ei;
    const int* dst = ei + E;

    const int T = 256;
    int nb = (n + SCAN_CHUNK - 1) / SCAN_CHUNK;

    k_zero<<<(n + T - 1) / T, T>>>(n);
    k_deg<<<(E + T - 1) / T, T>>>(dst, E);
    k_blocksum<<<nb, SCAN_CHUNK>>>(n);
    k_scan_bsum<<<1, 32>>>(nb, n, E);
    k_scan<<<nb, SCAN_CHUNK>>>((const float4*)x, n);
    k_fill<<<(E + T - 1) / T, T>>>(src, dst, E);
    k_layer1<<<(n + 7) / 8, T>>>(W1, b1, W2, n);
    k_final<<<(n + 7) / 8, T>>>(b2, Wf, bf, out, n);
}

// round 3
// speedup vs baseline: 1.2817x; 1.2817x over previous
#include <cuda_runtime.h>
#include <cuda_bf16.h>

#define NMAX 100000
#define EMAX 1600000
#define SCAN_CHUNK 1024
#define NB_MAX ((NMAX + SCAN_CHUNK - 1) / SCAN_CHUNK)   // 98

// ---------------------------------------------------------------------------
// Scratch (device globals — allocation is forbidden in kernel_launch)
// ---------------------------------------------------------------------------
__device__ int   g_deg[NMAX];
__device__ int   g_off[NMAX + 1];     // CSR row offsets (by dst)
__device__ int   g_cur[NMAX];         // fill cursors
__device__ int   g_csrc[EMAX];        // CSR column = src node per edge
__device__ int   g_bsum[NB_MAX + 1];  // block sums for scan
__device__ float g_dinv[NMAX];
__device__ float g_xs[NMAX * 4];      // x * dinv  (pre-scaled layer-1 sources)
__device__ float g_a1[NMAX * 4];      // layer-1 aggregate (reds from k_fill)
__device__ float g_h2s[NMAX * 32];    // (relu(v@W1+b1) @ W2) * dinv

// ---------------------------------------------------------------------------
// red.global.add.v4.f32 (sm_90+): fire-and-forget vector atomic add
// ---------------------------------------------------------------------------
__device__ __forceinline__ void red_add_v4(float* p, float4 v) {
    asm volatile(
        "{\n\t"
        ".reg .u64 q;\n\t"
        "cvta.to.global.u64 q, %0;\n\t"
        "red.global.add.v4.f32 [q], {%1, %2, %3, %4};\n\t"
        "}"
        :: "l"(p), "f"(v.x), "f"(v.y), "f"(v.z), "f"(v.w)
        : "memory");
}

// ---------------------------------------------------------------------------
// K0: zero deg counters + a1 accumulators
// ---------------------------------------------------------------------------
__global__ void k_zero(int n) {
    int i = blockIdx.x * blockDim.x + threadIdx.x;
    if (i < n) g_deg[i] = 0;
    if (i < n * 4) g_a1[i] = 0.0f;
}

// ---------------------------------------------------------------------------
// K1: degree over dst (vectorized int4; E % 4 == 0 for this problem,
//     tail handled scalar just in case)
// ---------------------------------------------------------------------------
__global__ void k_deg(const int* __restrict__ dst, int E) {
    int i = blockIdx.x * blockDim.x + threadIdx.x;
    int e = i * 4;
    if (e + 4 <= E) {
        int4 d = *(const int4*)&dst[e];
        atomicAdd(&g_deg[d.x], 1);
        atomicAdd(&g_deg[d.y], 1);
        atomicAdd(&g_deg[d.z], 1);
        atomicAdd(&g_deg[d.w], 1);
    } else {
        for (; e < E; e++) atomicAdd(&g_deg[dst[e]], 1);
    }
}

// ---------------------------------------------------------------------------
// K2a: per-chunk (1024) sums of deg
// ---------------------------------------------------------------------------
__global__ void k_blocksum(int n) {
    __shared__ int sw[32];
    int t = threadIdx.x;
    int i = blockIdx.x * SCAN_CHUNK + t;
    int v = (i < n) ? g_deg[i] : 0;
#pragma unroll
    for (int o = 16; o > 0; o >>= 1) v += __shfl_xor_sync(0xffffffff, v, o);
    if ((t & 31) == 0) sw[t >> 5] = v;
    __syncthreads();
    if (t < 32) {
        int s = (t < SCAN_CHUNK / 32) ? sw[t] : 0;
#pragma unroll
        for (int o = 16; o > 0; o >>= 1) s += __shfl_xor_sync(0xffffffff, s, o);
        if (t == 0) g_bsum[blockIdx.x] = s;
    }
}

// ---------------------------------------------------------------------------
// K2b: parallel exclusive scan of block sums (nb <= 128), 1 block / 128 thr
// ---------------------------------------------------------------------------
__global__ void k_scan_bsum(int nb, int n, int E) {
    __shared__ int sw[4];
    int t = threadIdx.x;
    int v = (t < nb) ? g_bsum[t] : 0;
    int orig = v;
    // inclusive scan within warp
#pragma unroll
    for (int o = 1; o < 32; o <<= 1) {
        int y = __shfl_up_sync(0xffffffff, v, o);
        if ((t & 31) >= o) v += y;
    }
    if ((t & 31) == 31) sw[t >> 5] = v;
    __syncthreads();
    int add = 0;
    int w = t >> 5;
    for (int k = 0; k < w; k++) add += sw[k];
    if (t < nb) g_bsum[t] = v + add - orig;   // exclusive
    if (t == 0) g_off[n] = E;
}

// ---------------------------------------------------------------------------
// K2c: per-chunk exclusive scan -> g_off, g_cur; also dinv + x pre-scale
// ---------------------------------------------------------------------------
__global__ void k_scan(const float4* __restrict__ x4, int n) {
    __shared__ int sh[SCAN_CHUNK];
    int t = threadIdx.x;
    int i = blockIdx.x * SCAN_CHUNK + t;
    int v = (i < n) ? g_deg[i] : 0;
    sh[t] = v;
    __syncthreads();
    for (int o = 1; o < SCAN_CHUNK; o <<= 1) {
        int y = (t >= o) ? sh[t - o] : 0;
        __syncthreads();
        sh[t] += y;
        __syncthreads();
    }
    if (i < n) {
        int exc = g_bsum[blockIdx.x] + sh[t] - v;
        g_off[i] = exc;
        g_cur[i] = exc;
        float di = rsqrtf((float)(v + 1));   // +1 self-loop
        g_dinv[i] = di;
        float4 xv = x4[i];
        xv.x *= di; xv.y *= di; xv.z *= di; xv.w *= di;
        *(float4*)&g_xs[i * 4] = xv;
    }
}

// ---------------------------------------------------------------------------
// K3: bucket-fill CSR + fused layer-1 scatter:
//     csrc[pos] = src[e];  a1[dst] += xs[src]   (red.v4, 16B/edge)
// ---------------------------------------------------------------------------
__global__ void k_fill(const int* __restrict__ src,
                       const int* __restrict__ dst, int E) {
    int e = blockIdx.x * blockDim.x + threadIdx.x;
    if (e >= E) return;
    int s = src[e], d = dst[e];
    int pos = atomicAdd(&g_cur[d], 1);
    g_csrc[pos] = s;
    float4 xv = *(const float4*)&g_xs[s * 4];
    red_add_v4(&g_a1[d * 4], xv);
}

// ---------------------------------------------------------------------------
// K4: layer-1 transform, thread per node (no edge loop):
//     v   = dinv*(a1 + xs)          [4]
//     h1  = relu(v @ W1 + b1)       [64]
//     h2s = (h1 @ W2) * dinv        [32]
// ---------------------------------------------------------------------------
__global__ void __launch_bounds__(256) k_layer1(
        const float* __restrict__ W1,   // [4,64]
        const float* __restrict__ b1,   // [64]
        const float* __restrict__ W2,   // [64,32]
        int n) {
    __shared__ float sW1[4 * 64];
    __shared__ float sb1[64];
    __shared__ float sW2[64 * 32];
    int t = threadIdx.x;
    for (int i = t; i < 256;  i += 256) sW1[i] = W1[i];
    if (t < 64) sb1[t] = b1[t];
    for (int i = t; i < 2048; i += 256) sW2[i] = W2[i];
    __syncthreads();

    int i = blockIdx.x * 256 + t;
    if (i >= n) return;

    float di = g_dinv[i];
    float4 a  = *(const float4*)&g_a1[i * 4];
    float4 xv = *(const float4*)&g_xs[i * 4];
    float v0 = (a.x + xv.x) * di;
    float v1 = (a.y + xv.y) * di;
    float v2 = (a.z + xv.z) * di;
    float v3 = (a.w + xv.w) * di;

    float acc[32];
#pragma unroll
    for (int j = 0; j < 32; j++) acc[j] = 0.0f;

#pragma unroll 8
    for (int f = 0; f < 64; f++) {
        float h = fmaf(v0, sW1[f],
                  fmaf(v1, sW1[64 + f],
                  fmaf(v2, sW1[128 + f],
                  fmaf(v3, sW1[192 + f], sb1[f]))));
        h = fmaxf(h, 0.0f);
        const float4* w2row = (const float4*)&sW2[f * 32];
#pragma unroll
        for (int j = 0; j < 8; j++) {
            float4 w = w2row[j];
            acc[4 * j + 0] = fmaf(h, w.x, acc[4 * j + 0]);
            acc[4 * j + 1] = fmaf(h, w.y, acc[4 * j + 1]);
            acc[4 * j + 2] = fmaf(h, w.z, acc[4 * j + 2]);
            acc[4 * j + 3] = fmaf(h, w.w, acc[4 * j + 3]);
        }
    }

    float4* o = (float4*)&g_h2s[i * 32];
#pragma unroll
    for (int j = 0; j < 8; j++)
        o[j] = make_float4(acc[4 * j] * di, acc[4 * j + 1] * di,
                           acc[4 * j + 2] * di, acc[4 * j + 3] * di);
}

// ---------------------------------------------------------------------------
// K5: fused layer 2 + final linear (warp per node, lane = feature):
//     h2  = relu(dinv*(sum_s h2s[s] + h2s[node]) + b2)    [32]
//     out = relu(h2 @ Wf + bf)                            [32]
//     CSR gather: each edge = one coalesced 128B line, no atomics.
// ---------------------------------------------------------------------------
__global__ void __launch_bounds__(256) k_final(
        const float* __restrict__ b2,   // [32]
        const float* __restrict__ Wf,   // [32,32]
        const float* __restrict__ bf,   // [32]
        float* __restrict__ out, int n) {
    __shared__ float sWf[32 * 32];
    __shared__ float sb2[32];
    __shared__ float sbf[32];
    __shared__ float sh[8][32];
    int t = threadIdx.x;
    for (int i = t; i < 1024; i += 256) sWf[i] = Wf[i];
    if (t < 32) { sb2[t] = b2[t]; sbf[t] = bf[t]; }
    __syncthreads();

    int w = t >> 5, j = t & 31;
    int node = blockIdx.x * 8 + w;
    if (node >= n) return;

    int beg = g_off[node], end = g_off[node + 1];
    float acc = 0.0f;
    int i = beg;
    // 8-edge unroll for MLP
    for (; i + 8 <= end; i += 8) {
        int s0 = g_csrc[i + 0], s1 = g_csrc[i + 1];
        int s2 = g_csrc[i + 2], s3 = g_csrc[i + 3];
        int s4 = g_csrc[i + 4], s5 = g_csrc[i + 5];
        int s6 = g_csrc[i + 6], s7 = g_csrc[i + 7];
        float m0 = g_h2s[s0 * 32 + j], m1 = g_h2s[s1 * 32 + j];
        float m2 = g_h2s[s2 * 32 + j], m3 = g_h2s[s3 * 32 + j];
        float m4 = g_h2s[s4 * 32 + j], m5 = g_h2s[s5 * 32 + j];
        float m6 = g_h2s[s6 * 32 + j], m7 = g_h2s[s7 * 32 + j];
        acc += ((m0 + m1) + (m2 + m3)) + ((m4 + m5) + (m6 + m7));
    }
    for (; i < end; i++)
        acc += g_h2s[g_csrc[i] * 32 + j];

    float di = g_dinv[node];
    float h = fmaxf(fmaf(di, acc + g_h2s[node * 32 + j], sb2[j]), 0.0f);
    sh[w][j] = h;
    __syncwarp();

    float o = sbf[j];
#pragma unroll
    for (int k = 0; k < 32; k++)
        o = fmaf(sh[w][k], sWf[k * 32 + j], o);
    out[node * 32 + j] = fmaxf(o, 0.0f);
}

// ---------------------------------------------------------------------------
// Launch
// Inputs: x[N,4], edge_index[2,E], W1[4,64], b1[64], W2[64,32], b2[32],
//         Wf[32,32], bf[32]       Output: [N,32] float32
// ---------------------------------------------------------------------------
extern "C" void kernel_launch(void* const* d_in, const int* in_sizes, int n_in,
                              void* d_out, int out_size) {
    const float* x  = (const float*)d_in[0];
    const int*   ei = (const int*)d_in[1];
    const float* W1 = (const float*)d_in[2];
    const float* b1 = (const float*)d_in[3];
    const float* W2 = (const float*)d_in[4];
    const float* b2 = (const float*)d_in[5];
    const float* Wf = (const float*)d_in[6];
    const float* bf = (const float*)d_in[7];
    float* out = (float*)d_out;

    int n = in_sizes[0] / 4;
    int E = in_sizes[1] / 2;
    const int* src = ei;
    const int* dst = ei + E;

    const int T = 256;
    int nb = (n + SCAN_CHUNK - 1) / SCAN_CHUNK;

    k_zero<<<(n * 4 + T - 1) / T, T>>>(n);
    k_deg<<<((E + 3) / 4 + T - 1) / T, T>>>(dst, E);
    k_blocksum<<<nb, SCAN_CHUNK>>>(n);
    k_scan_bsum<<<1, 128>>>(nb, n, E);
    k_scan<<<nb, SCAN_CHUNK>>>((const float4*)x, n);
    k_fill<<<(E + T - 1) / T, T>>>(src, dst, E);
    k_layer1<<<(n + T - 1) / T, T>>>(W1, b1, W2, n);
    k_final<<<(n + 7) / 8, T>>>(b2, Wf, bf, out, n);
}

// round 4
// speedup vs baseline: 1.3244x; 1.0333x over previous
#include <cuda_runtime.h>
#include <cuda_bf16.h>

#define NMAX 100000
#define EMAX 1600000
#define SCAN_CHUNK 1024

// ---------------------------------------------------------------------------
// Scratch (device globals — zero-initialized at module load; every kernel
// that consumes a scratch array restores it to zero, so no k_zero is needed
// and the invariant holds across CUDA-graph replays).
// ---------------------------------------------------------------------------
__device__ int   g_deg[NMAX];
__device__ int   g_off[NMAX];        // CSR range begin (by dst)
__device__ int   g_end[NMAX];        // CSR range end
__device__ int   g_cur[NMAX];        // fill cursors
__device__ int   g_csrc[EMAX];       // CSR column = src node per edge
__device__ int   g_base;             // global edge-slot counter
__device__ float g_dinv[NMAX];
__device__ float g_xs[NMAX * 4];     // x * dinv (pre-scaled layer-1 sources)
__device__ float g_a1[NMAX * 4];     // layer-1 aggregate (REDs from k_fill)
__device__ float g_h2s[NMAX * 32];   // (relu(v@W1+b1) @ W2) * dinv

// ---------------------------------------------------------------------------
// red.global.add.v4.f32 (sm_90+): fire-and-forget vector atomic add
// ---------------------------------------------------------------------------
__device__ __forceinline__ void red_add_v4(float* p, float4 v) {
    asm volatile(
        "{\n\t"
        ".reg .u64 q;\n\t"
        "cvta.to.global.u64 q, %0;\n\t"
        "red.global.add.v4.f32 [q], {%1, %2, %3, %4};\n\t"
        "}"
        :: "l"(p), "f"(v.x), "f"(v.y), "f"(v.z), "f"(v.w)
        : "memory");
}

// ---------------------------------------------------------------------------
// K1: degree over dst (int4 vectorized); also resets g_base for this call
// ---------------------------------------------------------------------------
__global__ void k_deg(const int* __restrict__ dst, int E) {
    int i = blockIdx.x * blockDim.x + threadIdx.x;
    if (i == 0) g_base = 0;
    int e = i * 4;
    if (e + 4 <= E) {
        int4 d = *(const int4*)&dst[e];
        atomicAdd(&g_deg[d.x], 1);
        atomicAdd(&g_deg[d.y], 1);
        atomicAdd(&g_deg[d.z], 1);
        atomicAdd(&g_deg[d.w], 1);
    } else {
        for (; e < E; e++) atomicAdd(&g_deg[dst[e]], 1);
    }
}

// ---------------------------------------------------------------------------
// K2: single-pass chunked scan with atomic base assignment.
//     Per 1024-chunk: local exclusive scan, block grabs a global base via
//     atomicAdd. Ranges need not be monotonic across chunks — g_end stores
//     the explicit end. Also computes dinv, pre-scales x, and ZEROES g_deg.
// ---------------------------------------------------------------------------
__global__ void __launch_bounds__(SCAN_CHUNK) k_scan(const float4* __restrict__ x4, int n) {
    __shared__ int swarp[32];
    __shared__ int sbase;
    int t = threadIdx.x;
    int lane = t & 31, wid = t >> 5;
    int i = blockIdx.x * SCAN_CHUNK + t;
    int v = (i < n) ? g_deg[i] : 0;

    int inc = v;
#pragma unroll
    for (int o = 1; o < 32; o <<= 1) {
        int y = __shfl_up_sync(0xffffffff, inc, o);
        if (lane >= o) inc += y;
    }
    if (lane == 31) swarp[wid] = inc;
    __syncthreads();
    if (t < 32) {
        int wv = swarp[t];
        int winc = wv;
#pragma unroll
        for (int o = 1; o < 32; o <<= 1) {
            int y = __shfl_up_sync(0xffffffff, winc, o);
            if (t >= o) winc += y;
        }
        swarp[t] = winc - wv;                     // exclusive warp base
        if (t == 31) sbase = atomicAdd(&g_base, winc);  // winc = block total
    }
    __syncthreads();

    if (i < n) {
        int beg = sbase + swarp[wid] + (inc - v);
        g_off[i] = beg;
        g_cur[i] = beg;
        g_end[i] = beg + v;
        float di = rsqrtf((float)(v + 1));        // +1 self-loop
        g_dinv[i] = di;
        float4 xv = x4[i];
        xv.x *= di; xv.y *= di; xv.z *= di; xv.w *= di;
        *(float4*)&g_xs[i * 4] = xv;
        g_deg[i] = 0;                             // restore scratch invariant
    }
}

// ---------------------------------------------------------------------------
// K3: bucket-fill CSR + fused layer-1 scatter:
//     csrc[pos] = src[e];  a1[dst] += xs[src]   (red.v4, 16B/edge)
// ---------------------------------------------------------------------------
__global__ void k_fill(const int* __restrict__ src,
                       const int* __restrict__ dst, int E) {
    int e = blockIdx.x * blockDim.x + threadIdx.x;
    if (e >= E) return;
    int s = src[e], d = dst[e];
    int pos = atomicAdd(&g_cur[d], 1);
    g_csrc[pos] = s;
    float4 xv = *(const float4*)&g_xs[s * 4];
    red_add_v4(&g_a1[d * 4], xv);
}

// ---------------------------------------------------------------------------
// K4: layer-1 transform, thread per node (no edge loop):
//     v = dinv*(a1 + xs);  h1 = relu(v@W1+b1);  h2s = (h1@W2)*dinv
//     Also zeroes g_a1 after consuming it.
// ---------------------------------------------------------------------------
__global__ void __launch_bounds__(256) k_layer1(
        const float* __restrict__ W1,   // [4,64]
        const float* __restrict__ b1,   // [64]
        const float* __restrict__ W2,   // [64,32]
        int n) {
    __shared__ float sW1[4 * 64];
    __shared__ float sb1[64];
    __shared__ float sW2[64 * 32];
    int t = threadIdx.x;
    for (int i = t; i < 256;  i += 256) sW1[i] = W1[i];
    if (t < 64) sb1[t] = b1[t];
    for (int i = t; i < 2048; i += 256) sW2[i] = W2[i];
    __syncthreads();

    int i = blockIdx.x * 256 + t;
    if (i >= n) return;

    float di = g_dinv[i];
    float4 a  = *(const float4*)&g_a1[i * 4];
    float4 xv = *(const float4*)&g_xs[i * 4];
    *(float4*)&g_a1[i * 4] = make_float4(0.f, 0.f, 0.f, 0.f);  // restore zeros
    float v0 = (a.x + xv.x) * di;
    float v1 = (a.y + xv.y) * di;
    float v2 = (a.z + xv.z) * di;
    float v3 = (a.w + xv.w) * di;

    float acc[32];
#pragma unroll
    for (int j = 0; j < 32; j++) acc[j] = 0.0f;

#pragma unroll 8
    for (int f = 0; f < 64; f++) {
        float h = fmaf(v0, sW1[f],
                  fmaf(v1, sW1[64 + f],
                  fmaf(v2, sW1[128 + f],
                  fmaf(v3, sW1[192 + f], sb1[f]))));
        h = fmaxf(h, 0.0f);
        const float4* w2row = (const float4*)&sW2[f * 32];
#pragma unroll
        for (int j = 0; j < 8; j++) {
            float4 w = w2row[j];
            acc[4 * j + 0] = fmaf(h, w.x, acc[4 * j + 0]);
            acc[4 * j + 1] = fmaf(h, w.y, acc[4 * j + 1]);
            acc[4 * j + 2] = fmaf(h, w.z, acc[4 * j + 2]);
            acc[4 * j + 3] = fmaf(h, w.w, acc[4 * j + 3]);
        }
    }

    float4* o = (float4*)&g_h2s[i * 32];
#pragma unroll
    for (int j = 0; j < 8; j++)
        o[j] = make_float4(acc[4 * j] * di, acc[4 * j + 1] * di,
                           acc[4 * j + 2] * di, acc[4 * j + 3] * di);
}

// ---------------------------------------------------------------------------
// K5: fused layer 2 + final linear (warp per node, lane = feature):
//     h2  = relu(dinv*(sum_s h2s[s] + h2s[node]) + b2)
//     out = relu(h2 @ Wf + bf)
//     CSR gather: each edge = one coalesced 128B line, no atomics.
// ---------------------------------------------------------------------------
__global__ void __launch_bounds__(256) k_final(
        const float* __restrict__ b2,   // [32]
        const float* __restrict__ Wf,   // [32,32]
        const float* __restrict__ bf,   // [32]
        float* __restrict__ out, int n) {
    __shared__ float sWf[32 * 32];
    __shared__ float sb2[32];
    __shared__ float sbf[32];
    __shared__ float sh[8][32];
    int t = threadIdx.x;
    for (int i = t; i < 1024; i += 256) sWf[i] = Wf[i];
    if (t < 32) { sb2[t] = b2[t]; sbf[t] = bf[t]; }
    __syncthreads();

    int w = t >> 5, j = t & 31;
    int node = blockIdx.x * 8 + w;
    if (node >= n) return;

    int beg = g_off[node], end = g_end[node];
    float acc = 0.0f;
    int i = beg;
    for (; i + 8 <= end; i += 8) {
        int s0 = g_csrc[i + 0], s1 = g_csrc[i + 1];
        int s2 = g_csrc[i + 2], s3 = g_csrc[i + 3];
        int s4 = g_csrc[i + 4], s5 = g_csrc[i + 5];
        int s6 = g_csrc[i + 6], s7 = g_csrc[i + 7];
        float m0 = g_h2s[s0 * 32 + j], m1 = g_h2s[s1 * 32 + j];
        float m2 = g_h2s[s2 * 32 + j], m3 = g_h2s[s3 * 32 + j];
        float m4 = g_h2s[s4 * 32 + j], m5 = g_h2s[s5 * 32 + j];
        float m6 = g_h2s[s6 * 32 + j], m7 = g_h2s[s7 * 32 + j];
        acc += ((m0 + m1) + (m2 + m3)) + ((m4 + m5) + (m6 + m7));
    }
    for (; i < end; i++)
        acc += g_h2s[g_csrc[i] * 32 + j];

    float di = g_dinv[node];
    float h = fmaxf(fmaf(di, acc + g_h2s[node * 32 + j], sb2[j]), 0.0f);
    sh[w][j] = h;
    __syncwarp();

    float o = sbf[j];
#pragma unroll
    for (int k = 0; k < 32; k++)
        o = fmaf(sh[w][k], sWf[k * 32 + j], o);
    out[node * 32 + j] = fmaxf(o, 0.0f);
}

// ---------------------------------------------------------------------------
// Launch — 5 kernels total
// Inputs: x[N,4], edge_index[2,E], W1[4,64], b1[64], W2[64,32], b2[32],
//         Wf[32,32], bf[32]       Output: [N,32] float32
// ---------------------------------------------------------------------------
extern "C" void kernel_launch(void* const* d_in, const int* in_sizes, int n_in,
                              void* d_out, int out_size) {
    const float* x  = (const float*)d_in[0];
    const int*   ei = (const int*)d_in[1];
    const float* W1 = (const float*)d_in[2];
    const float* b1 = (const float*)d_in[3];
    const float* W2 = (const float*)d_in[4];
    const float* b2 = (const float*)d_in[5];
    const float* Wf = (const float*)d_in[6];
    const float* bf = (const float*)d_in[7];
    float* out = (float*)d_out;

    int n = in_sizes[0] / 4;
    int E = in_sizes[1] / 2;
    const int* src = ei;
    const int* dst = ei + E;

    const int T = 256;
    int nb = (n + SCAN_CHUNK - 1) / SCAN_CHUNK;

    k_deg<<<((E + 3) / 4 + T - 1) / T, T>>>(dst, E);
    k_scan<<<nb, SCAN_CHUNK>>>((const float4*)x, n);
    k_fill<<<(E + T - 1) / T, T>>>(src, dst, E);
    k_layer1<<<(n + T - 1) / T, T>>>(W1, b1, W2, n);
    k_final<<<(n + 7) / 8, T>>>(b2, Wf, bf, out, n);
}